// round 17
// baseline (speedup 1.0000x reference)
#include <cuda_runtime.h>
#include <cstdint>
#include <cstddef>

#define B_TOTAL 65536
#define NGRAPH  64
#define NNODES  2048
#define NEDGES  16384
#define META    64
#define TXD     8
#define NOISE   128
#define RROWS   64    // rows per block in main kernel (warp owns 16)
#define NFEAT   41
#define SPAD    68    // padded row stride for 64 rows
#define ESPLIT  8
#define GK      128   // gcn_gemm K-splits
#define GROWS   16    // rows per gcn_gemm block

typedef unsigned long long ull;

// Scratch: [deg_part | agg_part | dinv | g_go]; partials are [g][sp][node]
#define PART_FLOATS (NGRAPH * ESPLIT * NNODES)          // 1048576
#define DINV_FLOATS (NGRAPH * NNODES)                   // 131072
#define SCRATCH_FLOATS (2 * PART_FLOATS + DINV_FLOATS + NGRAPH * NOISE)
__device__ float scratch[SCRATCH_FLOATS];
#define DEG_PART (scratch)
#define AGG_PART (scratch + PART_FLOATS)
#define DINV     (scratch + 2 * PART_FLOATS)
#define G_GO     (scratch + 2 * PART_FLOATS + DINV_FLOATS)

// ---------- PDL ----------
__device__ __forceinline__ void pdl_wait() {
    asm volatile("griddepcontrol.wait;" ::: "memory");
}

// ---------- f32x2 helpers ----------
__device__ __forceinline__ ull pack2(float lo, float hi) {
    ull r; asm("mov.b64 %0, {%1,%2};" : "=l"(r) : "f"(lo), "f"(hi)); return r;
}
__device__ __forceinline__ ull fma2(ull a, ull b, ull c) {
    ull d; asm("fma.rn.f32x2 %0, %1, %2, %3;" : "=l"(d) : "l"(a), "l"(b), "l"(c)); return d;
}
__device__ __forceinline__ void unpack2(ull v, float& lo, float& hi) {
    asm("mov.b64 {%0,%1}, %2;" : "=f"(lo), "=f"(hi) : "l"(v));
}
__device__ __forceinline__ void stcs4(float* p, float4 v) {
    asm volatile("st.global.cs.v4.f32 [%0], {%1,%2,%3,%4};"
                 :: "l"(p), "f"(v.x), "f"(v.y), "f"(v.z), "f"(v.w) : "memory");
}

// ============================================================================
// k_deg (chain head, no wait): per-split smem edge count -> dense STG of
// deg_part. Split-0 blocks also zero g_go (consumed 2 grids later).
// ============================================================================
__global__ __launch_bounds__(256) void k_deg(const int* __restrict__ edges) {
    __shared__ int cnt[NNODES];
    const int g  = blockIdx.x >> 3;
    const int sp = blockIdx.x & 7;
    const int tid = threadIdx.x;

    const int4* dst4 = reinterpret_cast<const int4*>(
        edges + (size_t)g * 2 * NEDGES + NEDGES) + sp * (NEDGES / ESPLIT / 4);
    int4 d0 = __ldg(&dst4[tid]);
    int4 d1 = __ldg(&dst4[256 + tid]);

    if (sp == 0 && tid < NOISE) G_GO[g * NOISE + tid] = 0.f;

    #pragma unroll
    for (int i = 0; i < NNODES / 256; i++) cnt[i * 256 + tid] = 0;
    __syncthreads();

    atomicAdd(&cnt[d0.x], 1);
    atomicAdd(&cnt[d0.y], 1);
    atomicAdd(&cnt[d0.z], 1);
    atomicAdd(&cnt[d0.w], 1);
    atomicAdd(&cnt[d1.x], 1);
    atomicAdd(&cnt[d1.y], 1);
    atomicAdd(&cnt[d1.z], 1);
    atomicAdd(&cnt[d1.w], 1);
    __syncthreads();

    float* op = DEG_PART + (size_t)blockIdx.x * NNODES;
    #pragma unroll
    for (int i = 0; i < NNODES / 256; i++)
        op[i * 256 + tid] = (float)cnt[i * 256 + tid];
}

// ============================================================================
// k_norm: edge loads (prologue) -> wait -> sum deg partials -> dinv in smem ->
// smem-accumulate split's norm contributions -> dense STG of agg_part.
// sp==0 blocks also persist dinv.
// ============================================================================
__global__ __launch_bounds__(256) void k_norm(const int* __restrict__ edges) {
    __shared__ float dinv_s[NNODES];
    __shared__ float agg_s[NNODES];
    const int g  = blockIdx.x >> 3;
    const int sp = blockIdx.x & 7;
    const int tid = threadIdx.x;

    const int* base = edges + (size_t)g * 2 * NEDGES;
    const int4* src4 = reinterpret_cast<const int4*>(base) + sp * (NEDGES / ESPLIT / 4);
    const int4* dst4 = reinterpret_cast<const int4*>(base + NEDGES) + sp * (NEDGES / ESPLIT / 4);
    int4 s0 = __ldg(&src4[tid]);
    int4 s1 = __ldg(&src4[256 + tid]);
    int4 d0 = __ldg(&dst4[tid]);
    int4 d1 = __ldg(&dst4[256 + tid]);

    pdl_wait();   // deg_part complete

    const float* dp = DEG_PART + (size_t)g * ESPLIT * NNODES;
    #pragma unroll
    for (int i = 0; i < NNODES / 256; i++) {
        int n = i * 256 + tid;
        float s = 1.0f;   // self loop
        #pragma unroll
        for (int spp = 0; spp < ESPLIT; spp++)
            s += __ldg(&dp[spp * NNODES + n]);
        dinv_s[n] = rsqrtf(s);
        agg_s[n]  = 0.f;
    }
    __syncthreads();

    atomicAdd(&agg_s[d0.x], dinv_s[s0.x] * dinv_s[d0.x]);
    atomicAdd(&agg_s[d0.y], dinv_s[s0.y] * dinv_s[d0.y]);
    atomicAdd(&agg_s[d0.z], dinv_s[s0.z] * dinv_s[d0.z]);
    atomicAdd(&agg_s[d0.w], dinv_s[s0.w] * dinv_s[d0.w]);
    atomicAdd(&agg_s[d1.x], dinv_s[s1.x] * dinv_s[d1.x]);
    atomicAdd(&agg_s[d1.y], dinv_s[s1.y] * dinv_s[d1.y]);
    atomicAdd(&agg_s[d1.z], dinv_s[s1.z] * dinv_s[d1.z]);
    atomicAdd(&agg_s[d1.w], dinv_s[s1.w] * dinv_s[d1.w]);
    __syncthreads();

    float* op = AGG_PART + (size_t)blockIdx.x * NNODES;
    #pragma unroll
    for (int i = 0; i < NNODES / 256; i++)
        op[i * 256 + tid] = agg_s[i * 256 + tid];

    if (sp == 0) {
        float* dv = DINV + (size_t)g * NNODES;
        #pragma unroll
        for (int i = 0; i < NNODES / 256; i++)
            dv[i * 256 + tid] = dinv_s[i * 256 + tid];
    }
}

// ============================================================================
// gcn_gemm: 1024 blocks = 128 K-splits (16 rows) x 8 graph-groups.
// Pass A (pre-wait): wsum. Wait. dinv load + 8 agg partials -> 16x8 FMA.
// ============================================================================
__global__ __launch_bounds__(128) void gcn_gemm(
    const float* __restrict__ embW, const float* __restrict__ gwp,
    const float* __restrict__ gbp)
{
    __shared__ float aggs[8][GROWS];
    const int tid = threadIdx.x;
    const int ks  = blockIdx.x & (GK - 1);
    const int gsp = blockIdx.x >> 7;

    const float* wb = embW + (size_t)ks * GROWS * NOISE + tid;
    float wsum = 0.f;
    #pragma unroll
    for (int n = 0; n < GROWS; n++)
        wsum += __ldg(wb + (size_t)n * NOISE);

    pdl_wait();   // agg_part + dinv complete

    {
        int j = tid >> 4, n = tid & (GROWS - 1);
        int g = gsp * 8 + j;
        int node = ks * GROWS + n;
        float dv = __ldg(&DINV[(size_t)g * NNODES + node]);
        const float* ap = AGG_PART + (size_t)g * ESPLIT * NNODES + node;
        float asum = dv * dv;   // self-loop term
        #pragma unroll
        for (int sp = 0; sp < ESPLIT; sp++)
            asum += __ldg(&ap[sp * NNODES]);
        aggs[j][n] = asum;
    }
    __syncthreads();

    float acc[8] = {0.f, 0.f, 0.f, 0.f, 0.f, 0.f, 0.f, 0.f};
    #pragma unroll
    for (int n = 0; n < GROWS; n++) {
        float wv = __ldg(wb + (size_t)n * NOISE);
        #pragma unroll
        for (int j = 0; j < 8; j++)
            acc[j] = fmaf(aggs[j][n], wv, acc[j]);
    }
    const float w = gwp[0], b = gbp[0];
    const float bterm = b * wsum;
    #pragma unroll
    for (int j = 0; j < 8; j++)
        atomicAdd(&G_GO[(gsp * 8 + j) * NOISE + tid], fmaf(w, acc[j], bterm));
}

// ============================================================================
// noise_main (R5 tiling, best measured 32.3us): 128 threads, 64 rows/block,
// warp owns 16 rows (8 packed pairs), acc[8][4]. Staging + trig MLP pre-wait;
// wait; g_go gather fused into acc epilogue-free flow; streaming stores.
// ============================================================================
__global__ __launch_bounds__(128, 4) void noise_main(
    const int*   __restrict__ gid,   const float* __restrict__ chain,
    const float* __restrict__ td,    const float* __restrict__ tx,
    const float* __restrict__ trigW, const float* __restrict__ trigb,
    const float* __restrict__ embW,  const float* __restrict__ embb,
    float* __restrict__ out)
{
    __shared__ __align__(16) float td_s[META][SPAD];
    __shared__ __align__(16) float feat_s[NFEAT][SPAD];  // 0=chain,1..32=trig,33..40=tx
    __shared__ int gs[RROWS];

    const int tid = threadIdx.x;
    const int r0  = blockIdx.x * RROWS;
    const int lane = tid & 31;
    const int w    = tid >> 5;

    // ---- stage inputs (transposed; rotated components -> 2-way conflicts) ----
    {
        const float4* tdg = reinterpret_cast<const float4*>(td + (size_t)r0 * META);
        #pragma unroll
        for (int it = 0; it < 8; it++) {
            int i = it * 128 + tid;
            int r = i >> 4;           // row 0..63
            int q = i & 15;           // m-quad
            float4 v = tdg[i];        // coalesced
            float vv[4] = {v.x, v.y, v.z, v.w};
            #pragma unroll
            for (int j = 0; j < 4; j++) {
                int c = ((q >> 1) + j) & 3;
                td_s[4 * q + c][r] = vv[c];
            }
        }
        {
            const float4* txg = reinterpret_cast<const float4*>(tx + (size_t)r0 * TXD);
            int r = tid >> 1, q = tid & 1;
            float4 v = txg[tid];
            feat_s[33 + 4 * q + 0][r] = v.x;
            feat_s[33 + 4 * q + 1][r] = v.y;
            feat_s[33 + 4 * q + 2][r] = v.z;
            feat_s[33 + 4 * q + 3][r] = v.w;
        }
        if (tid < RROWS) {
            feat_s[0][tid] = chain[r0 + tid];
            gs[tid] = gid[r0 + tid];
        }
    }
    __syncthreads();

    // ---- phase 1 (pre-wait): trig = relu(td @ trig_W + trig_b), 8 pairs/warp ----
    {
        const int k = lane;
        float tb = __ldg(&trigb[k]);
        ull acc[8];
        #pragma unroll
        for (int u = 0; u < 8; u++) acc[u] = pack2(tb, tb);
        #pragma unroll 8
        for (int m = 0; m < META; m++) {
            float wv = __ldg(&trigW[m * 32 + k]);
            ull wd = pack2(wv, wv);
            ulonglong2 t0 = *reinterpret_cast<const ulonglong2*>(&td_s[m][16 * w]);
            ulonglong2 t1 = *reinterpret_cast<const ulonglong2*>(&td_s[m][16 * w + 4]);
            ulonglong2 t2 = *reinterpret_cast<const ulonglong2*>(&td_s[m][16 * w + 8]);
            ulonglong2 t3 = *reinterpret_cast<const ulonglong2*>(&td_s[m][16 * w + 12]);
            acc[0] = fma2(wd, t0.x, acc[0]);
            acc[1] = fma2(wd, t0.y, acc[1]);
            acc[2] = fma2(wd, t1.x, acc[2]);
            acc[3] = fma2(wd, t1.y, acc[3]);
            acc[4] = fma2(wd, t2.x, acc[4]);
            acc[5] = fma2(wd, t2.y, acc[5]);
            acc[6] = fma2(wd, t3.x, acc[6]);
            acc[7] = fma2(wd, t3.y, acc[7]);
        }
        #pragma unroll
        for (int u = 0; u < 8; u++) {
            float a, b2;
            unpack2(acc[u], a, b2);
            *reinterpret_cast<ull*>(&feat_s[1 + k][16 * w + 2 * u]) =
                pack2(fmaxf(a, 0.f), fmaxf(b2, 0.f));
        }
    }
    __syncthreads();

    pdl_wait();   // g_go complete

    // ---- phase 2: output GEMM over 41 features, 8 pairs x 4 cols / thread ----
    {
        const int jq = lane;          // cols 4*jq..4*jq+3
        const float4 eb = __ldg(reinterpret_cast<const float4*>(&embb[4 * jq]));

        ull acc[8][4];
        #pragma unroll
        for (int u = 0; u < 8; u++) {
            int ra = 16 * w + 2 * u, rb = ra + 1;
            float4 ga = __ldg(reinterpret_cast<const float4*>(&G_GO[gs[ra] * NOISE + 4 * jq]));
            float4 gb = __ldg(reinterpret_cast<const float4*>(&G_GO[gs[rb] * NOISE + 4 * jq]));
            acc[u][0] = pack2(ga.x + eb.x, gb.x + eb.x);
            acc[u][1] = pack2(ga.y + eb.y, gb.y + eb.y);
            acc[u][2] = pack2(ga.z + eb.z, gb.z + eb.z);
            acc[u][3] = pack2(ga.w + eb.w, gb.w + eb.w);
        }

        const float4* wrow = reinterpret_cast<const float4*>(embW + (size_t)2048 * NOISE) + jq;
        #pragma unroll 4
        for (int k = 0; k < NFEAT; k++) {
            float4 wv = __ldg(wrow + (size_t)k * (NOISE / 4));
            ull wd0 = pack2(wv.x, wv.x);
            ull wd1 = pack2(wv.y, wv.y);
            ull wd2 = pack2(wv.z, wv.z);
            ull wd3 = pack2(wv.w, wv.w);
            ulonglong2 t0 = *reinterpret_cast<const ulonglong2*>(&feat_s[k][16 * w]);
            ulonglong2 t1 = *reinterpret_cast<const ulonglong2*>(&feat_s[k][16 * w + 4]);
            ulonglong2 t2 = *reinterpret_cast<const ulonglong2*>(&feat_s[k][16 * w + 8]);
            ulonglong2 t3 = *reinterpret_cast<const ulonglong2*>(&feat_s[k][16 * w + 12]);
            ull tp[8] = {t0.x, t0.y, t1.x, t1.y, t2.x, t2.y, t3.x, t3.y};
            #pragma unroll
            for (int u = 0; u < 8; u++) {
                acc[u][0] = fma2(wd0, tp[u], acc[u][0]);
                acc[u][1] = fma2(wd1, tp[u], acc[u][1]);
                acc[u][2] = fma2(wd2, tp[u], acc[u][2]);
                acc[u][3] = fma2(wd3, tp[u], acc[u][3]);
            }
        }

        #pragma unroll
        for (int u = 0; u < 8; u++) {
            size_t ra = (size_t)(r0 + 16 * w + 2 * u);
            float4 lo, hi;
            unpack2(acc[u][0], lo.x, hi.x);
            unpack2(acc[u][1], lo.y, hi.y);
            unpack2(acc[u][2], lo.z, hi.z);
            unpack2(acc[u][3], lo.w, hi.w);
            stcs4(out + ra * NOISE + 4 * jq, lo);
            stcs4(out + (ra + 1) * NOISE + 4 * jq, hi);
        }
    }
}

// ============================================================================
extern "C" void kernel_launch(void* const* d_in, const int* in_sizes, int n_in,
                              void* d_out, int out_size) {
    (void)in_sizes; (void)n_in; (void)out_size;
    const int*   gid   = (const int*)  d_in[0];
    const float* chain = (const float*)d_in[1];
    const float* td    = (const float*)d_in[2];
    const float* tx    = (const float*)d_in[3];
    const int*   edges = (const int*)  d_in[4];
    const float* gw    = (const float*)d_in[5];
    const float* gb    = (const float*)d_in[6];
    const float* trigW = (const float*)d_in[7];
    const float* trigb = (const float*)d_in[8];
    const float* embW  = (const float*)d_in[9];
    const float* embb  = (const float*)d_in[10];
    float* out = (float*)d_out;

    cudaLaunchAttribute pattr;
    pattr.id = cudaLaunchAttributeProgrammaticStreamSerialization;
    pattr.val.programmaticStreamSerializationAllowed = 1;

    // chain head: plain launch, no wait inside
    k_deg<<<NGRAPH * ESPLIT, 256>>>(edges);

    cudaLaunchConfig_t cfg = {};
    cfg.stream   = 0;
    cfg.attrs    = &pattr;
    cfg.numAttrs = 1;

    cfg.blockDim = dim3(256, 1, 1);
    cfg.gridDim  = dim3(NGRAPH * ESPLIT, 1, 1);
    cudaLaunchKernelEx(&cfg, k_norm, edges);

    cfg.blockDim = dim3(128, 1, 1);
    cfg.gridDim  = dim3(GK * 8, 1, 1);
    cudaLaunchKernelEx(&cfg, gcn_gemm, embW, gw, gb);

    cfg.gridDim = dim3(B_TOTAL / RROWS, 1, 1);
    cudaLaunchKernelEx(&cfg, noise_main, gid, chain, td, tx, trigW, trigb,
                       embW, embb, out);
}